// round 16
// baseline (speedup 1.0000x reference)
#include <cuda_runtime.h>
#include <cuda_fp16.h>
#include <cstdint>

// ============================ problem sizes ============================
#define BATCH 4096
#define INF   1024
#define OUTF  1024
#define KBASIS 8
#define KDIM2 (INF * (KBASIS - 1))   // 7168: k=0 (T0==1) folded into bias

// ======================= device scratch (no allocs) ====================
__device__ __half g_A[(size_t)BATCH * KDIM2];   // fp16 basis  [4096][k-1][i]
__device__ __half g_W[(size_t)OUTF * KDIM2];    // fp16 weights [1024][k-1][i]
__device__ float  g_part[OUTF * 2];             // per-o half-sums of W[o,:,0]

// ============================ PTX helpers ==============================
__device__ __forceinline__ uint32_t smem_u32(const void* p) {
    uint32_t a;
    asm("{ .reg .u64 t; cvta.to.shared.u64 t, %1; cvt.u32.u64 %0, t; }" : "=r"(a) : "l"(p));
    return a;
}

__device__ __forceinline__ float fast_tanh(float v) {
    float r;
    asm("tanh.approx.f32 %0, %1;" : "=f"(r) : "f"(v));
    return r;
}

#define CP_ASYNC_CG16(smem, gptr) \
    asm volatile("cp.async.cg.shared.global [%0], [%1], 16;" :: "r"(smem), "l"(gptr) : "memory")

#define CP_ASYNC_COMMIT() \
    asm volatile("cp.async.commit_group;" ::: "memory")

#define CP_ASYNC_WAIT(n) \
    asm volatile("cp.async.wait_group %0;" :: "n"(n) : "memory")

#define LDSM_X4(r0, r1, r2, r3, addr) \
    asm volatile("ldmatrix.sync.aligned.m8n8.x4.shared.b16 {%0,%1,%2,%3}, [%4];" \
        : "=r"(r0), "=r"(r1), "=r"(r2), "=r"(r3) : "r"(addr))

// m16n8k16 fp16 MMA (row-major A, col-major B), fp32 accumulate in place.
#define MMA_F16(d, a, b) \
    asm volatile("mma.sync.aligned.m16n8k16.row.col.f32.f16.f16.f32 " \
        "{%0,%1,%2,%3}, {%4,%5,%6,%7}, {%8,%9}, {%0,%1,%2,%3};" \
        : "+f"((d)[0]), "+f"((d)[1]), "+f"((d)[2]), "+f"((d)[3]) \
        : "r"((a)[0]), "r"((a)[1]), "r"((a)[2]), "r"((a)[3]), \
          "r"((b)[0]), "r"((b)[1]))

// ===== kernel 1: basis (4 el/thread) + weight repack + k0 partials =====
constexpr int BASIS_BLOCKS = BATCH;                     // 4096
constexpr int WCONV_BLOCKS = (OUTF * INF / 2) / 256;    // 2048

__global__ void __launch_bounds__(256) prep_kernel(const float* __restrict__ x,
                                                   const float* __restrict__ w) {
    const int tid = threadIdx.x;
    if (blockIdx.x < BASIS_BLOCKS) {
        const int b  = blockIdx.x;
        const int i0 = tid * 4;
        float4 xv = reinterpret_cast<const float4*>(x + (size_t)b * INF)[tid];
        float t[4] = { fast_tanh(xv.x), fast_tanh(xv.y), fast_tanh(xv.z), fast_tanh(xv.w) };
        float Tp[4] = {1.0f, 1.0f, 1.0f, 1.0f};   // T_{k-1}
        float Tc[4] = {t[0], t[1], t[2], t[3]};    // T_k
        __half* base = g_A + (size_t)b * KDIM2 + i0;
#pragma unroll
        for (int j = 0; j < KBASIS - 1; j++) {     // emit T_1..T_7
            __half2 h0 = __floats2half2_rn(Tc[0], Tc[1]);
            __half2 h1 = __floats2half2_rn(Tc[2], Tc[3]);
            uint2 pk = { *reinterpret_cast<uint32_t*>(&h0), *reinterpret_cast<uint32_t*>(&h1) };
            *reinterpret_cast<uint2*>(base + j * INF) = pk;
#pragma unroll
            for (int l = 0; l < 4; l++) {
                float Tn = 2.0f * t[l] * Tc[l] - Tp[l];
                Tp[l] = Tc[l];
                Tc[l] = Tn;
            }
        }
    } else {
        const int bid2 = blockIdx.x - BASIS_BLOCKS;
        const int o  = bid2 >> 1;          // output feature
        const int ih = bid2 & 1;           // i-half (512 i's per block)
        const int i  = ih * 512 + tid * 2; // first of this thread's 2 i's
        const float4* src = reinterpret_cast<const float4*>(w + ((size_t)o * INF + i) * KBASIS);
        float4 a0 = src[0], a1 = src[1];   // i:   k = 0..3, 4..7
        float4 b0 = src[2], b1 = src[3];   // i+1: k = 0..3, 4..7
        __half2* dst = reinterpret_cast<__half2*>(g_W + (size_t)o * KDIM2 + ih * 512) + tid;
        dst[0 * (INF / 2)] = __floats2half2_rn(a0.y, b0.y);
        dst[1 * (INF / 2)] = __floats2half2_rn(a0.z, b0.z);
        dst[2 * (INF / 2)] = __floats2half2_rn(a0.w, b0.w);
        dst[3 * (INF / 2)] = __floats2half2_rn(a1.x, b1.x);
        dst[4 * (INF / 2)] = __floats2half2_rn(a1.y, b1.y);
        dst[5 * (INF / 2)] = __floats2half2_rn(a1.z, b1.z);
        dst[6 * (INF / 2)] = __floats2half2_rn(a1.w, b1.w);
        // deterministic tree-reduce of k=0 column (2-elem pre-sum per thread)
        __shared__ float red[256];
        red[tid] = a0.x + b0.x;
        __syncthreads();
#pragma unroll
        for (int d = 128; d > 0; d >>= 1) {
            if (tid < d) red[tid] += red[tid + d];
            __syncthreads();
        }
        if (tid == 0) g_part[o * 2 + ih] = red[0];
    }
}

// ========================= kernel 2: fp16 GEMM =========================
// C[4096,1024] = g_A[4096,7168] * g_W[1024,7168]^T + bias + k0-partials
// CTA tile 256x128 (grid = 128 CTAs, single wave), K-chunk 128 halves
// (256B rows, XOR-swizzled), 2 stages (192 KB), 8 warps (4M x 2N),
// warptile 64x64, register double-buffered ldmatrix fragments
// (ks-loop unroll limited to 2 to bound address-hoisting registers).
constexpr int TILE_K  = 128;                         // halves per chunk
constexpr int KCHUNKS = KDIM2 / TILE_K;              // 56
constexpr int ROW_B   = 256;                         // bytes per SMEM row
constexpr int A_BYTES = 256 * ROW_B;                 // 64 KB
constexpr int B_BYTES = 128 * ROW_B;                 // 32 KB
constexpr int STAGE_BYTES = A_BYTES + B_BYTES;       // 96 KB
constexpr int DYN_SMEM    = 2 * STAGE_BYTES;         // 192 KB

__global__ void __launch_bounds__(256, 1) gemm_kernel(const float* __restrict__ bias,
                                                      float* __restrict__ out) {
    extern __shared__ char smem[];
    const int tid  = threadIdx.x;
    const int wid  = tid >> 5;
    const int lane = tid & 31;
    const int g    = lane >> 2;    // groupID (0..7)
    const int tg   = lane & 3;     // threadID in group (0..3)
    const int nTile = blockIdx.x;  // 0..7  (x-fastest: share A block-row via L2)
    const int mTile = blockIdx.y;  // 0..15
    const int mbase = (wid >> 1) * 64;  // warp M offset in CTA tile (0..192)
    const int nbase = (wid & 1) * 64;   // warp N offset in CTA tile (0/64)

    const __half* __restrict__ Ag = g_A + (size_t)mTile * 256 * KDIM2;
    const __half* __restrict__ Bg = g_W + (size_t)nTile * 128 * KDIM2;
    const uint32_t sbase = smem_u32(smem);

    float acc[4][8][4];
#pragma unroll
    for (int mt = 0; mt < 4; mt++)
#pragma unroll
        for (int nt = 0; nt < 8; nt++)
#pragma unroll
            for (int j = 0; j < 4; j++) acc[mt][nt][j] = 0.0f;

    // ---- per-thread ldmatrix lane addressing ----
    const int arow  = mbase + (lane & 15);                        // + mt*16
    const int akh   = lane >> 4;
    const int aswz  = arow & 7;
    const int brow0 = nbase + (lane & 7) + ((lane >> 4) & 1) * 8; // + pair*16
    const int bkh   = (lane >> 3) & 1;
    const int bswz  = brow0 & 7;

    // ---- async copy of one K-chunk into stage s ----
    // A: 256 rows x 16 segs = 4096 16B copies (16/thread); B: 2048 (8/thread).
    auto issue = [&](int kc, int s) {
        const uint32_t so = sbase + (uint32_t)s * STAGE_BYTES;
#pragma unroll
        for (int i = 0; i < 16; i++) {
            int idx = tid + i * 256;
            int row = idx >> 4;
            int seg = idx & 15;
            uint32_t dst = so + row * ROW_B + ((seg ^ (row & 7)) * 16);
            CP_ASYNC_CG16(dst, Ag + (size_t)row * KDIM2 + kc * TILE_K + seg * 8);
        }
#pragma unroll
        for (int i = 0; i < 8; i++) {
            int idx = tid + i * 256;
            int row = idx >> 4;
            int seg = idx & 15;
            uint32_t dst = so + A_BYTES + row * ROW_B + ((seg ^ (row & 7)) * 16);
            CP_ASYNC_CG16(dst, Bg + (size_t)row * KDIM2 + kc * TILE_K + seg * 8);
        }
        CP_ASYNC_COMMIT();
    };

    uint32_t af[2][4][4];
    uint32_t bf[2][4][4];

    // Prologue: chunk 0 into stage 0.
    issue(0, 0);

#pragma unroll 1
    for (int kc = 0; kc < KCHUNKS; kc++) {
        CP_ASYNC_WAIT(0);
        __syncthreads();
        if (kc + 1 < KCHUNKS) issue(kc + 1, (kc + 1) & 1);

        const uint32_t so = sbase + (uint32_t)(kc & 1) * STAGE_BYTES;

        // fragment loader for k16-step ks into buffer b
        auto ldfrag = [&](int ks, int b) {
#pragma unroll
            for (int mt = 0; mt < 4; mt++) {
                uint32_t addr = so + (arow + mt * 16) * ROW_B
                              + (((ks * 2 + akh) ^ aswz) * 16);
                LDSM_X4(af[b][mt][0], af[b][mt][1], af[b][mt][2], af[b][mt][3], addr);
            }
#pragma unroll
            for (int pair = 0; pair < 4; pair++) {
                uint32_t addr = so + A_BYTES + (brow0 + pair * 16) * ROW_B
                              + (((ks * 2 + bkh) ^ bswz) * 16);
                LDSM_X4(bf[b][pair][0], bf[b][pair][1], bf[b][pair][2], bf[b][pair][3], addr);
            }
        };

        ldfrag(0, 0);
#pragma unroll 2
        for (int ks = 0; ks < TILE_K / 16; ks++) {   // 8 k16-steps
            const int cur = ks & 1;
            if (ks < TILE_K / 16 - 1) ldfrag(ks + 1, cur ^ 1);
#pragma unroll
            for (int mt = 0; mt < 4; mt++)
#pragma unroll
                for (int nt = 0; nt < 8; nt++)
                    MMA_F16(acc[mt][nt], af[cur][mt], &bf[cur][nt >> 1][(nt & 1) * 2]);
        }
    }

    // ------------------------------ epilogue ------------------------------
    float bv[8][2];
#pragma unroll
    for (int nt = 0; nt < 8; nt++) {
#pragma unroll
        for (int h = 0; h < 2; h++) {
            int col = nTile * 128 + nbase + nt * 8 + 2 * tg + h;
            const float* p = g_part + col * 2;
            bv[nt][h] = bias[col] + (p[0] + p[1]);
        }
    }
#pragma unroll
    for (int mt = 0; mt < 4; mt++) {
        int row0 = mTile * 256 + mbase + mt * 16 + g;
#pragma unroll
        for (int nt = 0; nt < 8; nt++) {
            int col = nTile * 128 + nbase + nt * 8 + 2 * tg;
            float2 v0, v1;
            v0.x = acc[mt][nt][0] + bv[nt][0];
            v0.y = acc[mt][nt][1] + bv[nt][1];
            v1.x = acc[mt][nt][2] + bv[nt][0];
            v1.y = acc[mt][nt][3] + bv[nt][1];
            *reinterpret_cast<float2*>(out + (size_t)row0 * OUTF + col) = v0;
            *reinterpret_cast<float2*>(out + (size_t)(row0 + 8) * OUTF + col) = v1;
        }
    }
}

// ============================ launcher =================================
extern "C" void kernel_launch(void* const* d_in, const int* in_sizes, int n_in,
                              void* d_out, int out_size) {
    const float* x    = (const float*)d_in[0];
    const float* w    = (const float*)d_in[1];
    const float* bias = (const float*)d_in[2];
    float* out        = (float*)d_out;

    cudaFuncSetAttribute(gemm_kernel, cudaFuncAttributeMaxDynamicSharedMemorySize, DYN_SMEM);

    prep_kernel<<<BASIS_BLOCKS + WCONV_BLOCKS, 256>>>(x, w);
    gemm_kernel<<<dim3(OUTF / 128, BATCH / 256), 256, DYN_SMEM>>>(bias, out);
}

// round 17
// speedup vs baseline: 1.0556x; 1.0556x over previous
#include <cuda_runtime.h>
#include <cuda_fp16.h>
#include <cstdint>

// ============================ problem sizes ============================
#define BATCH 4096
#define INF   1024
#define OUTF  1024
#define KBASIS 8
#define KDIM2 (INF * (KBASIS - 1))   // 7168: k=0 (T0==1) folded into bias

// ======================= device scratch (no allocs) ====================
__device__ __half g_A[(size_t)BATCH * KDIM2];   // fp16 basis  [4096][k-1][i]
__device__ __half g_W[(size_t)OUTF * KDIM2];    // fp16 weights [1024][k-1][i]
__device__ float  g_part[OUTF * 2];             // per-o half-sums of W[o,:,0]

// ============================ PTX helpers ==============================
__device__ __forceinline__ uint32_t smem_u32(const void* p) {
    uint32_t a;
    asm("{ .reg .u64 t; cvta.to.shared.u64 t, %1; cvt.u32.u64 %0, t; }" : "=r"(a) : "l"(p));
    return a;
}

__device__ __forceinline__ float fast_tanh(float v) {
    float r;
    asm("tanh.approx.f32 %0, %1;" : "=f"(r) : "f"(v));
    return r;
}

#define CP_ASYNC_CG16(smem, gptr) \
    asm volatile("cp.async.cg.shared.global [%0], [%1], 16;" :: "r"(smem), "l"(gptr) : "memory")

#define CP_ASYNC_COMMIT() \
    asm volatile("cp.async.commit_group;" ::: "memory")

#define CP_ASYNC_WAIT(n) \
    asm volatile("cp.async.wait_group %0;" :: "n"(n) : "memory")

#define LDSM_X4(r0, r1, r2, r3, addr) \
    asm volatile("ldmatrix.sync.aligned.m8n8.x4.shared.b16 {%0,%1,%2,%3}, [%4];" \
        : "=r"(r0), "=r"(r1), "=r"(r2), "=r"(r3) : "r"(addr))

// m16n8k16 fp16 MMA (row-major A, col-major B), fp32 accumulate in place.
#define MMA_F16(d, a, b) \
    asm volatile("mma.sync.aligned.m16n8k16.row.col.f32.f16.f16.f32 " \
        "{%0,%1,%2,%3}, {%4,%5,%6,%7}, {%8,%9}, {%0,%1,%2,%3};" \
        : "+f"((d)[0]), "+f"((d)[1]), "+f"((d)[2]), "+f"((d)[3]) \
        : "r"((a)[0]), "r"((a)[1]), "r"((a)[2]), "r"((a)[3]), \
          "r"((b)[0]), "r"((b)[1]))

// ===== kernel 1: basis (4 el/thread) + weight repack + k0 partials =====
constexpr int BASIS_BLOCKS = BATCH;                     // 4096
constexpr int WCONV_BLOCKS = (OUTF * INF / 2) / 256;    // 2048

__global__ void __launch_bounds__(256) prep_kernel(const float* __restrict__ x,
                                                   const float* __restrict__ w) {
    const int tid = threadIdx.x;
    if (blockIdx.x < BASIS_BLOCKS) {
        const int b  = blockIdx.x;
        const int i0 = tid * 4;
        float4 xv = reinterpret_cast<const float4*>(x + (size_t)b * INF)[tid];
        float t[4] = { fast_tanh(xv.x), fast_tanh(xv.y), fast_tanh(xv.z), fast_tanh(xv.w) };
        float Tp[4] = {1.0f, 1.0f, 1.0f, 1.0f};   // T_{k-1}
        float Tc[4] = {t[0], t[1], t[2], t[3]};    // T_k
        __half* base = g_A + (size_t)b * KDIM2 + i0;
#pragma unroll
        for (int j = 0; j < KBASIS - 1; j++) {     // emit T_1..T_7
            __half2 h0 = __floats2half2_rn(Tc[0], Tc[1]);
            __half2 h1 = __floats2half2_rn(Tc[2], Tc[3]);
            uint2 pk = { *reinterpret_cast<uint32_t*>(&h0), *reinterpret_cast<uint32_t*>(&h1) };
            *reinterpret_cast<uint2*>(base + j * INF) = pk;
#pragma unroll
            for (int l = 0; l < 4; l++) {
                float Tn = 2.0f * t[l] * Tc[l] - Tp[l];
                Tp[l] = Tc[l];
                Tc[l] = Tn;
            }
        }
    } else {
        const int bid2 = blockIdx.x - BASIS_BLOCKS;
        const int o  = bid2 >> 1;          // output feature
        const int ih = bid2 & 1;           // i-half (512 i's per block)
        const int i  = ih * 512 + tid * 2; // first of this thread's 2 i's
        const float4* src = reinterpret_cast<const float4*>(w + ((size_t)o * INF + i) * KBASIS);
        float4 a0 = src[0], a1 = src[1];   // i:   k = 0..3, 4..7
        float4 b0 = src[2], b1 = src[3];   // i+1: k = 0..3, 4..7
        __half2* dst = reinterpret_cast<__half2*>(g_W + (size_t)o * KDIM2 + ih * 512) + tid;
        dst[0 * (INF / 2)] = __floats2half2_rn(a0.y, b0.y);
        dst[1 * (INF / 2)] = __floats2half2_rn(a0.z, b0.z);
        dst[2 * (INF / 2)] = __floats2half2_rn(a0.w, b0.w);
        dst[3 * (INF / 2)] = __floats2half2_rn(a1.x, b1.x);
        dst[4 * (INF / 2)] = __floats2half2_rn(a1.y, b1.y);
        dst[5 * (INF / 2)] = __floats2half2_rn(a1.z, b1.z);
        dst[6 * (INF / 2)] = __floats2half2_rn(a1.w, b1.w);
        // deterministic tree-reduce of k=0 column (2-elem pre-sum per thread)
        __shared__ float red[256];
        red[tid] = a0.x + b0.x;
        __syncthreads();
#pragma unroll
        for (int d = 128; d > 0; d >>= 1) {
            if (tid < d) red[tid] += red[tid + d];
            __syncthreads();
        }
        if (tid == 0) g_part[o * 2 + ih] = red[0];
    }
}

// ========================= kernel 2: fp16 GEMM =========================
// C[4096,1024] = g_A[4096,7168] * g_W[1024,7168]^T + bias + k0-partials
// CTA tile 256x128 (grid = 128 CTAs, single wave), K-chunk 128 halves
// (256B rows, XOR-swizzled), 2 stages (192 KB), 8 warps (4M x 2N),
// warptile 64x64. Next-chunk cp.async burst issued AFTER ks0's MMAs are
// enqueued (tensor queue full), not in the shallow post-barrier window.
constexpr int TILE_K  = 128;                         // halves per chunk
constexpr int KCHUNKS = KDIM2 / TILE_K;              // 56
constexpr int ROW_B   = 256;                         // bytes per SMEM row
constexpr int A_BYTES = 256 * ROW_B;                 // 64 KB
constexpr int B_BYTES = 128 * ROW_B;                 // 32 KB
constexpr int STAGE_BYTES = A_BYTES + B_BYTES;       // 96 KB
constexpr int DYN_SMEM    = 2 * STAGE_BYTES;         // 192 KB

__global__ void __launch_bounds__(256, 1) gemm_kernel(const float* __restrict__ bias,
                                                      float* __restrict__ out) {
    extern __shared__ char smem[];
    const int tid  = threadIdx.x;
    const int wid  = tid >> 5;
    const int lane = tid & 31;
    const int g    = lane >> 2;    // groupID (0..7)
    const int tg   = lane & 3;     // threadID in group (0..3)
    const int nTile = blockIdx.x;  // 0..7  (x-fastest: share A block-row via L2)
    const int mTile = blockIdx.y;  // 0..15
    const int mbase = (wid >> 1) * 64;  // warp M offset in CTA tile (0..192)
    const int nbase = (wid & 1) * 64;   // warp N offset in CTA tile (0/64)

    const __half* __restrict__ Ag = g_A + (size_t)mTile * 256 * KDIM2;
    const __half* __restrict__ Bg = g_W + (size_t)nTile * 128 * KDIM2;
    const uint32_t sbase = smem_u32(smem);

    float acc[4][8][4];
#pragma unroll
    for (int mt = 0; mt < 4; mt++)
#pragma unroll
        for (int nt = 0; nt < 8; nt++)
#pragma unroll
            for (int j = 0; j < 4; j++) acc[mt][nt][j] = 0.0f;

    // ---- per-thread ldmatrix lane addressing ----
    const int arow  = mbase + (lane & 15);                        // + mt*16
    const int akh   = lane >> 4;
    const int aswz  = arow & 7;
    const int brow0 = nbase + (lane & 7) + ((lane >> 4) & 1) * 8; // + pair*16
    const int bkh   = (lane >> 3) & 1;
    const int bswz  = brow0 & 7;

    // ---- async copy of one K-chunk into stage s ----
    // A: 256 rows x 16 segs = 4096 16B copies (16/thread); B: 2048 (8/thread).
    auto issue = [&](int kc, int s) {
        const uint32_t so = sbase + (uint32_t)s * STAGE_BYTES;
#pragma unroll
        for (int i = 0; i < 16; i++) {
            int idx = tid + i * 256;
            int row = idx >> 4;
            int seg = idx & 15;
            uint32_t dst = so + row * ROW_B + ((seg ^ (row & 7)) * 16);
            CP_ASYNC_CG16(dst, Ag + (size_t)row * KDIM2 + kc * TILE_K + seg * 8);
        }
#pragma unroll
        for (int i = 0; i < 8; i++) {
            int idx = tid + i * 256;
            int row = idx >> 4;
            int seg = idx & 15;
            uint32_t dst = so + A_BYTES + row * ROW_B + ((seg ^ (row & 7)) * 16);
            CP_ASYNC_CG16(dst, Bg + (size_t)row * KDIM2 + kc * TILE_K + seg * 8);
        }
        CP_ASYNC_COMMIT();
    };

    // one k16-step: 8 LDSM + 32 MMA from stage base `so`
    auto kstep = [&](uint32_t so, int ks) {
        uint32_t af[4][4];
        uint32_t bf[4][4];
#pragma unroll
        for (int mt = 0; mt < 4; mt++) {
            uint32_t addr = so + (arow + mt * 16) * ROW_B
                          + (((ks * 2 + akh) ^ aswz) * 16);
            LDSM_X4(af[mt][0], af[mt][1], af[mt][2], af[mt][3], addr);
        }
#pragma unroll
        for (int pair = 0; pair < 4; pair++) {
            uint32_t addr = so + A_BYTES + (brow0 + pair * 16) * ROW_B
                          + (((ks * 2 + bkh) ^ bswz) * 16);
            LDSM_X4(bf[pair][0], bf[pair][1], bf[pair][2], bf[pair][3], addr);
        }
#pragma unroll
        for (int mt = 0; mt < 4; mt++)
#pragma unroll
            for (int nt = 0; nt < 8; nt++)
                MMA_F16(acc[mt][nt], af[mt], &bf[nt >> 1][(nt & 1) * 2]);
    };

    // Prologue: chunk 0 into stage 0.
    issue(0, 0);

#pragma unroll 1
    for (int kc = 0; kc < KCHUNKS; kc++) {
        CP_ASYNC_WAIT(0);
        __syncthreads();

        const uint32_t so = sbase + (uint32_t)(kc & 1) * STAGE_BYTES;

        // ks0 first: fill the tensor queue before spending issue slots on copies
        kstep(so, 0);

        if (kc + 1 < KCHUNKS) issue(kc + 1, (kc + 1) & 1);
        else CP_ASYNC_COMMIT();      // keep group count consistent

#pragma unroll
        for (int ks = 1; ks < TILE_K / 16; ks++)   // ks 1..7
            kstep(so, ks);
    }

    // ------------------------------ epilogue ------------------------------
    float bv[8][2];
#pragma unroll
    for (int nt = 0; nt < 8; nt++) {
#pragma unroll
        for (int h = 0; h < 2; h++) {
            int col = nTile * 128 + nbase + nt * 8 + 2 * tg + h;
            const float* p = g_part + col * 2;
            bv[nt][h] = bias[col] + (p[0] + p[1]);
        }
    }
#pragma unroll
    for (int mt = 0; mt < 4; mt++) {
        int row0 = mTile * 256 + mbase + mt * 16 + g;
#pragma unroll
        for (int nt = 0; nt < 8; nt++) {
            int col = nTile * 128 + nbase + nt * 8 + 2 * tg;
            float2 v0, v1;
            v0.x = acc[mt][nt][0] + bv[nt][0];
            v0.y = acc[mt][nt][1] + bv[nt][1];
            v1.x = acc[mt][nt][2] + bv[nt][0];
            v1.y = acc[mt][nt][3] + bv[nt][1];
            *reinterpret_cast<float2*>(out + (size_t)row0 * OUTF + col) = v0;
            *reinterpret_cast<float2*>(out + (size_t)(row0 + 8) * OUTF + col) = v1;
        }
    }
}

// ============================ launcher =================================
extern "C" void kernel_launch(void* const* d_in, const int* in_sizes, int n_in,
                              void* d_out, int out_size) {
    const float* x    = (const float*)d_in[0];
    const float* w    = (const float*)d_in[1];
    const float* bias = (const float*)d_in[2];
    float* out        = (float*)d_out;

    cudaFuncSetAttribute(gemm_kernel, cudaFuncAttributeMaxDynamicSharedMemorySize, DYN_SMEM);

    prep_kernel<<<BASIS_BLOCKS + WCONV_BLOCKS, 256>>>(x, w);
    gemm_kernel<<<dim3(OUTF / 128, BATCH / 256), 256, DYN_SMEM>>>(bias, out);
}